// round 1
// baseline (speedup 1.0000x reference)
#include <cuda_runtime.h>
#include <math.h>

// ---------------- problem constants ----------------
#define BSZ   2
#define SEQ   2048
#define DMODEL 1024
#define NHEAD 16
#define DHEAD 64
#define DFF   4096
#define MROWS (BSZ*SEQ)          // 4096
#define RES_SCALE 0.70710678118654752440f
#define LN_EPS 1e-5f

// ---------------- scratch (device globals; no allocations) ----------------
__device__ float g_h  [MROWS*DMODEL];
__device__ float g_q  [MROWS*DMODEL];
__device__ float g_k  [MROWS*DMODEL];
__device__ float g_v  [MROWS*DMODEL];
__device__ float g_ctx[MROWS*DMODEL];
__device__ float g_x1 [MROWS*DMODEL];
__device__ float g_f  [MROWS*DFF];

// ---------------- LayerNorm: one block per row ----------------
__global__ __launch_bounds__(256) void layernorm_kernel(
    const float* __restrict__ x, const float* __restrict__ g,
    const float* __restrict__ b, float* __restrict__ y)
{
    int row = blockIdx.x;
    int tid = threadIdx.x;
    const float4* xr = (const float4*)(x + (size_t)row * DMODEL);
    float4 v = xr[tid];                       // 256 threads * 4 = 1024
    float s  = v.x + v.y + v.z + v.w;
    float sq = v.x*v.x + v.y*v.y + v.z*v.z + v.w*v.w;
    #pragma unroll
    for (int o = 16; o > 0; o >>= 1) {
        s  += __shfl_xor_sync(0xffffffffu, s,  o);
        sq += __shfl_xor_sync(0xffffffffu, sq, o);
    }
    __shared__ float ss[8], ssq[8];
    int warp = tid >> 5, lane = tid & 31;
    if (lane == 0) { ss[warp] = s; ssq[warp] = sq; }
    __syncthreads();
    float ts = 0.f, tq = 0.f;
    #pragma unroll
    for (int i = 0; i < 8; i++) { ts += ss[i]; tq += ssq[i]; }
    float mean = ts * (1.0f / DMODEL);
    float var  = tq * (1.0f / DMODEL) - mean * mean;
    float rstd = rsqrtf(var + LN_EPS);

    float4 gv = ((const float4*)g)[tid];
    float4 bv = ((const float4*)b)[tid];
    float4 o4;
    o4.x = (v.x - mean) * rstd * gv.x + bv.x;
    o4.y = (v.y - mean) * rstd * gv.y + bv.y;
    o4.z = (v.z - mean) * rstd * gv.z + bv.z;
    o4.w = (v.w - mean) * rstd * gv.w + bv.w;
    ((float4*)(y + (size_t)row * DMODEL))[tid] = o4;
}

// ---------------- SGEMM 128x128x8, 256 thr, 8x8 reg tile ----------------
#define GBM 128
#define GBN 128
#define GBK 8
#define GTM 8
#define GTN 8

#define EPI_BIAS 0
#define EPI_GELU 1
#define EPI_RES  2

__global__ __launch_bounds__(256) void sgemm_kernel(
    int M, int N, int K,
    const float* __restrict__ A, const float* __restrict__ B,
    const float* __restrict__ bias, const float* __restrict__ res,
    float* __restrict__ C, float scale, int epi)
{
    __shared__ float As[GBK * GBM];   // transposed A tile
    __shared__ float Bs[GBK * GBN];

    int tid  = threadIdx.x;
    int cCol = blockIdx.x, cRow = blockIdx.y;

    const float* Ab = A + (size_t)cRow * GBM * K;
    const float* Bb = B + (size_t)cCol * GBN;

    int irA = tid >> 1;            // 0..127 (row in tile)
    int icA = (tid & 1) << 2;      // 0 or 4 (k offset)
    int irB = tid >> 5;            // 0..7   (k row)
    int icB = (tid & 31) << 2;     // 0..124 (col)
    int tRow = tid >> 4, tCol = tid & 15;

    float acc[GTM][GTN] = {};
    for (int k0 = 0; k0 < K; k0 += GBK) {
        float4 a = *(const float4*)(Ab + (size_t)irA * K + k0 + icA);
        As[(icA + 0) * GBM + irA] = a.x;
        As[(icA + 1) * GBM + irA] = a.y;
        As[(icA + 2) * GBM + irA] = a.z;
        As[(icA + 3) * GBM + irA] = a.w;
        *(float4*)(Bs + irB * GBN + icB) =
            *(const float4*)(Bb + (size_t)(k0 + irB) * N + icB);
        __syncthreads();

        #pragma unroll
        for (int kk = 0; kk < GBK; kk++) {
            float regM[GTM], regN[GTN];
            *(float4*)(regM)     = *(float4*)(As + kk * GBM + tRow * GTM);
            *(float4*)(regM + 4) = *(float4*)(As + kk * GBM + tRow * GTM + 4);
            *(float4*)(regN)     = *(float4*)(Bs + kk * GBN + tCol * GTN);
            *(float4*)(regN + 4) = *(float4*)(Bs + kk * GBN + tCol * GTN + 4);
            #pragma unroll
            for (int i = 0; i < GTM; i++)
                #pragma unroll
                for (int j = 0; j < GTN; j++)
                    acc[i][j] = fmaf(regM[i], regN[j], acc[i][j]);
        }
        __syncthreads();
    }

    int rowBase = cRow * GBM + tRow * GTM;
    int colBase = cCol * GBN + tCol * GTN;
    #pragma unroll
    for (int i = 0; i < GTM; i++) {
        size_t off = (size_t)(rowBase + i) * N + colBase;
        #pragma unroll
        for (int j = 0; j < GTN; j++) {
            float v = acc[i][j] + bias[colBase + j];
            if (epi == EPI_GELU) {
                float u = 0.7978845608028654f * (v + 0.044715f * v * v * v);
                v = 0.5f * v * (1.0f + tanhf(u));
            } else if (epi == EPI_RES) {
                v = res[off + j] + scale * v;
            }
            C[off + j] = v;
        }
    }
}

// ---------------- block-local causal attention (64x64 blocks) ----------------
// One CTA per (seq block, head, batch). Q/K/V layout: [B,S,H,64] (row stride 1024).
__global__ __launch_bounds__(256) void attn_kernel(
    const float* __restrict__ Q, const float* __restrict__ K,
    const float* __restrict__ V, float* __restrict__ O)
{
    __shared__ float Qs[64 * 64];   // Q row-major; later reused for V
    __shared__ float Kt[64 * 64];   // K transposed + rotation swizzle
    __shared__ float Ss[64 * 64];   // scores / probs

    int blk = blockIdx.x, h = blockIdx.y, b = blockIdx.z;
    int tid = threadIdx.x;
    size_t base = ((size_t)(b * SEQ + blk * 64) * NHEAD + h) * 64;

    for (int t = tid; t < 4096; t += 256) {
        int s = t >> 6, d = t & 63;
        Qs[s * 64 + d] = Q[base + (size_t)s * 1024 + d];
        Kt[d * 64 + ((s + d) & 63)] = K[base + (size_t)s * 1024 + d];
    }
    __syncthreads();

    int tr = tid >> 4, tc = tid & 15;
    // phase 1: S = Q K^T * 1/8
    float acc[4][4] = {};
    #pragma unroll 4
    for (int kk = 0; kk < 64; kk++) {
        float qa[4], kb[4];
        #pragma unroll
        for (int i = 0; i < 4; i++) qa[i] = Qs[(tr * 4 + i) * 64 + kk];
        #pragma unroll
        for (int j = 0; j < 4; j++) kb[j] = Kt[kk * 64 + ((tc * 4 + j + kk) & 63)];
        #pragma unroll
        for (int i = 0; i < 4; i++)
            #pragma unroll
            for (int j = 0; j < 4; j++)
                acc[i][j] = fmaf(qa[i], kb[j], acc[i][j]);
    }
    #pragma unroll
    for (int i = 0; i < 4; i++)
        #pragma unroll
        for (int j = 0; j < 4; j++)
            Ss[(tr * 4 + i) * 64 + tc * 4 + j] = acc[i][j] * 0.125f;
    __syncthreads();

    // phase 2: causal softmax per row (rows attend to cols <= row within block)
    int warp = tid >> 5, lane = tid & 31;
    for (int i = warp; i < 64; i += 8) {
        float v0 = Ss[i * 64 + lane];
        float v1 = Ss[i * 64 + lane + 32];
        bool  m0 = (lane <= i), m1 = (lane + 32 <= i);
        float a0 = m0 ? v0 : -INFINITY;
        float a1 = m1 ? v1 : -INFINITY;
        float m = fmaxf(a0, a1);
        #pragma unroll
        for (int o = 16; o > 0; o >>= 1) m = fmaxf(m, __shfl_xor_sync(0xffffffffu, m, o));
        float e0 = m0 ? expf(v0 - m) : 0.f;
        float e1 = m1 ? expf(v1 - m) : 0.f;
        float sum = e0 + e1;
        #pragma unroll
        for (int o = 16; o > 0; o >>= 1) sum += __shfl_xor_sync(0xffffffffu, sum, o);
        float inv = 1.0f / sum;
        Ss[i * 64 + lane]      = e0 * inv;
        Ss[i * 64 + lane + 32] = e1 * inv;
    }
    __syncthreads();

    // load V into Qs (Q no longer needed)
    for (int t = tid; t < 4096; t += 256) {
        int s = t >> 6, d = t & 63;
        Qs[s * 64 + d] = V[base + (size_t)s * 1024 + d];
    }
    __syncthreads();

    // phase 3: ctx = P V
    float cacc[4][4] = {};
    for (int j = 0; j < 64; j++) {
        float p[4], vv[4];
        #pragma unroll
        for (int i = 0; i < 4; i++) p[i] = Ss[(tr * 4 + i) * 64 + j];
        #pragma unroll
        for (int d = 0; d < 4; d++) vv[d] = Qs[j * 64 + tc * 4 + d];
        #pragma unroll
        for (int i = 0; i < 4; i++)
            #pragma unroll
            for (int d = 0; d < 4; d++)
                cacc[i][d] = fmaf(p[i], vv[d], cacc[i][d]);
    }
    #pragma unroll
    for (int i = 0; i < 4; i++)
        #pragma unroll
        for (int d = 0; d < 4; d++)
            O[base + (size_t)(tr * 4 + i) * 1024 + tc * 4 + d] = cacc[i][d];
}

// ---------------- launcher ----------------
extern "C" void kernel_launch(void* const* d_in, const int* in_sizes, int n_in,
                              void* d_out, int out_size)
{
    const float* x    = (const float*)d_in[0];
    // d_in[1] = mask_sa (block-causal structure is analytic; unused)
    const float* Wq   = (const float*)d_in[2];
    const float* bq   = (const float*)d_in[3];
    const float* Wk   = (const float*)d_in[4];
    const float* bk   = (const float*)d_in[5];
    const float* Wv   = (const float*)d_in[6];
    const float* bv   = (const float*)d_in[7];
    const float* Wo   = (const float*)d_in[8];
    const float* bo   = (const float*)d_in[9];
    const float* ln1g = (const float*)d_in[10];
    const float* ln1b = (const float*)d_in[11];
    const float* ln2g = (const float*)d_in[12];
    const float* ln2b = (const float*)d_in[13];
    const float* W1   = (const float*)d_in[14];
    const float* b1   = (const float*)d_in[15];
    const float* W2   = (const float*)d_in[16];
    const float* b2   = (const float*)d_in[17];
    float* out = (float*)d_out;

    float *ph, *pq, *pk, *pv, *pctx, *px1, *pf;
    cudaGetSymbolAddress((void**)&ph,   g_h);
    cudaGetSymbolAddress((void**)&pq,   g_q);
    cudaGetSymbolAddress((void**)&pk,   g_k);
    cudaGetSymbolAddress((void**)&pv,   g_v);
    cudaGetSymbolAddress((void**)&pctx, g_ctx);
    cudaGetSymbolAddress((void**)&px1,  g_x1);
    cudaGetSymbolAddress((void**)&pf,   g_f);

    // sublayer 1
    layernorm_kernel<<<MROWS, 256>>>(x, ln1g, ln1b, ph);
    dim3 gD(DMODEL / GBN, MROWS / GBM);     // N=1024 grids
    sgemm_kernel<<<gD, 256>>>(MROWS, DMODEL, DMODEL, ph, Wq, bq, nullptr, pq, 0.f, EPI_BIAS);
    sgemm_kernel<<<gD, 256>>>(MROWS, DMODEL, DMODEL, ph, Wk, bk, nullptr, pk, 0.f, EPI_BIAS);
    sgemm_kernel<<<gD, 256>>>(MROWS, DMODEL, DMODEL, ph, Wv, bv, nullptr, pv, 0.f, EPI_BIAS);
    attn_kernel<<<dim3(SEQ / 64, NHEAD, BSZ), 256>>>(pq, pk, pv, pctx);
    sgemm_kernel<<<gD, 256>>>(MROWS, DMODEL, DMODEL, pctx, Wo, bo, x, px1, RES_SCALE, EPI_RES);

    // sublayer 2
    layernorm_kernel<<<MROWS, 256>>>(px1, ln2g, ln2b, ph);
    dim3 gF(DFF / GBN, MROWS / GBM);
    sgemm_kernel<<<gF, 256>>>(MROWS, DFF, DMODEL, ph, W1, b1, nullptr, pf, 0.f, EPI_GELU);
    sgemm_kernel<<<gD, 256>>>(MROWS, DMODEL, DFF, pf, W2, b2, px1, out, RES_SCALE, EPI_RES);
}

// round 4
// speedup vs baseline: 3.3198x; 3.3198x over previous
#include <cuda_runtime.h>
#include <math.h>
#include <stdint.h>

// ---------------- problem constants ----------------
#define BSZ   2
#define SEQ   2048
#define DMODEL 1024
#define NHEAD 16
#define DHEAD 64
#define DFF   4096
#define MROWS (BSZ*SEQ)          // 4096
#define RES_SCALE 0.70710678118654752440f
#define LN_EPS 1e-5f

#define EPI_BIAS 0
#define EPI_GELU 1
#define EPI_RES  2

// ---------------- scratch (device globals; no allocations) ----------------
__device__ float g_h  [MROWS*DMODEL];
__device__ float g_q  [MROWS*DMODEL];
__device__ float g_k  [MROWS*DMODEL];
__device__ float g_v  [MROWS*DMODEL];
__device__ float g_ctx[MROWS*DMODEL];
__device__ float g_x1 [MROWS*DMODEL];
__device__ float g_f  [MROWS*DFF];
// transposed (tf32-rounded) weights, K-major rows
__device__ float g_wqt[DMODEL*DMODEL];
__device__ float g_wkt[DMODEL*DMODEL];
__device__ float g_wvt[DMODEL*DMODEL];
__device__ float g_wot[DMODEL*DMODEL];
__device__ float g_w1t[DMODEL*DFF];
__device__ float g_w2t[DMODEL*DFF];

// ---------------- helpers ----------------
__device__ __forceinline__ float to_tf32(float x) {
    uint32_t y;
    asm("cvt.rna.tf32.f32 %0, %1;" : "=r"(y) : "f"(x));
    return __uint_as_float(y);
}
__device__ __forceinline__ uint32_t smem_u32(const void* p) {
    uint32_t a;
    asm("{ .reg .u64 t; cvta.to.shared.u64 t, %1; cvt.u32.u64 %0, t; }" : "=r"(a) : "l"(p));
    return a;
}
__device__ __forceinline__ void cp16(uint32_t s, const void* g) {
    asm volatile("cp.async.cg.shared.global [%0], [%1], 16;" :: "r"(s), "l"(g));
}
#define CP_COMMIT() asm volatile("cp.async.commit_group;" ::: "memory")
#define CP_WAIT0()  asm volatile("cp.async.wait_group 0;" ::: "memory")

__device__ __forceinline__ void mma1688(float* c, const float* a, const float* b) {
    const uint32_t* A = reinterpret_cast<const uint32_t*>(a);
    const uint32_t* B = reinterpret_cast<const uint32_t*>(b);
    asm volatile(
        "mma.sync.aligned.m16n8k8.row.col.f32.tf32.tf32.f32 "
        "{%0,%1,%2,%3}, {%4,%5,%6,%7}, {%8,%9}, {%0,%1,%2,%3};"
        : "+f"(c[0]), "+f"(c[1]), "+f"(c[2]), "+f"(c[3])
        : "r"(A[0]), "r"(A[1]), "r"(A[2]), "r"(A[3]), "r"(B[0]), "r"(B[1]));
}

__device__ __forceinline__ float gelu1(float v) {
    float u = 0.7978845608028654f * (v + 0.044715f * v * v * v);
    return 0.5f * v * (1.0f + tanhf(u));
}

// ---------------- weight transpose (+tf32 rounding) ----------------
__global__ __launch_bounds__(256) void transpose_rt(
    const float* __restrict__ in, float* __restrict__ out, int K, int N)
{
    __shared__ float t[32][33];
    int n0 = blockIdx.x * 32, k0 = blockIdx.y * 32;
    int tx = threadIdx.x, ty = threadIdx.y;   // 32 x 8
    #pragma unroll
    for (int i = 0; i < 32; i += 8)
        t[ty + i][tx] = in[(size_t)(k0 + ty + i) * N + (n0 + tx)];
    __syncthreads();
    #pragma unroll
    for (int i = 0; i < 32; i += 8)
        out[(size_t)(n0 + ty + i) * K + (k0 + tx)] = to_tf32(t[tx][ty + i]);
}

// ---------------- LayerNorm (tf32-rounded output) ----------------
__global__ __launch_bounds__(256) void layernorm_kernel(
    const float* __restrict__ x, const float* __restrict__ g,
    const float* __restrict__ b, float* __restrict__ y)
{
    int row = blockIdx.x;
    int tid = threadIdx.x;
    const float4* xr = (const float4*)(x + (size_t)row * DMODEL);
    float4 v = xr[tid];
    float s  = v.x + v.y + v.z + v.w;
    float sq = v.x*v.x + v.y*v.y + v.z*v.z + v.w*v.w;
    #pragma unroll
    for (int o = 16; o > 0; o >>= 1) {
        s  += __shfl_xor_sync(0xffffffffu, s,  o);
        sq += __shfl_xor_sync(0xffffffffu, sq, o);
    }
    __shared__ float ss[8], ssq[8];
    int warp = tid >> 5, lane = tid & 31;
    if (lane == 0) { ss[warp] = s; ssq[warp] = sq; }
    __syncthreads();
    float ts = 0.f, tq = 0.f;
    #pragma unroll
    for (int i = 0; i < 8; i++) { ts += ss[i]; tq += ssq[i]; }
    float mean = ts * (1.0f / DMODEL);
    float var  = tq * (1.0f / DMODEL) - mean * mean;
    float rstd = rsqrtf(var + LN_EPS);

    float4 gv = ((const float4*)g)[tid];
    float4 bv = ((const float4*)b)[tid];
    float4 o4;
    o4.x = to_tf32((v.x - mean) * rstd * gv.x + bv.x);
    o4.y = to_tf32((v.y - mean) * rstd * gv.y + bv.y);
    o4.z = to_tf32((v.z - mean) * rstd * gv.z + bv.z);
    o4.w = to_tf32((v.w - mean) * rstd * gv.w + bv.w);
    ((float4*)(y + (size_t)row * DMODEL))[tid] = o4;
}

// ---------------- tf32 mma.sync GEMM: C[M,N] = A[M,K] * Bt[N,K]^T ----------------
// CTA tile 128x128, BK=32, double-buffered cp.async, warp tile 64x32 (m16n8k8).
// smem per operand tile: [128 rows][36 floats] (32 K-floats + 4 pad).
#define TS_F   (128*36)          // floats per tile buffer
#define TS_B   (TS_F*4)          // bytes (18432)
#define SMEM_GEMM (4*TS_B)       // A0,B0,A1,B1 = 73728

__device__ __forceinline__ void tile_load(
    uint32_t sbase, const float* __restrict__ gA, const float* __restrict__ gB,
    int buf, int kt, int K, int tid)
{
    uint32_t a_s = sbase + buf * 2 * TS_B;
    uint32_t b_s = a_s + TS_B;
    const float* ga = gA + kt * 32;
    const float* gb = gB + kt * 32;
    #pragma unroll
    for (int i = 0; i < 4; i++) {
        int id = tid + i * 256;          // 0..1023
        int row = id >> 3, c4 = (id & 7) << 2;
        uint32_t so = (uint32_t)(row * 36 + c4) * 4u;
        cp16(a_s + so, ga + (size_t)row * K + c4);
        cp16(b_s + so, gb + (size_t)row * K + c4);
    }
}

__global__ __launch_bounds__(256, 2) void gemm_mma(
    int K, int N, const float* __restrict__ A, const float* __restrict__ Bt,
    const float* __restrict__ bias, const float* __restrict__ res,
    float* __restrict__ C, float scale, int epi)
{
    extern __shared__ char smem[];
    const uint32_t sb = smem_u32(smem);
    const int tid = threadIdx.x, wid = tid >> 5, lane = tid & 31;
    const int gid = lane >> 2, tig = lane & 3;
    const int wm = wid >> 2, wn = wid & 3;          // warp grid 2(m) x 4(n)
    const int cN = blockIdx.x, cM = blockIdx.y;
    const int NT = K >> 5;

    const float* gA = A  + (size_t)cM * 128 * K;
    const float* gB = Bt + (size_t)cN * 128 * K;

    float acc[4][4][4] = {};
    const int mrow = wm * 64 + gid;                 // fragment row base
    const int nrow = wn * 32 + gid;                 // fragment col base

    tile_load(sb, gA, gB, 0, 0, K, tid);
    CP_COMMIT();

    for (int kt = 0; kt < NT; kt++) {
        CP_WAIT0();
        __syncthreads();
        if (kt + 1 < NT) {
            tile_load(sb, gA, gB, (kt + 1) & 1, kt + 1, K, tid);
            CP_COMMIT();
        }
        const float* As = (const float*)(smem + (kt & 1) * 2 * TS_B);
        const float* Bs = As + TS_F;
        #pragma unroll
        for (int ks = 0; ks < 4; ks++) {
            const int k0 = ks * 8 + tig;
            float a[4][4], b[4][2];
            #pragma unroll
            for (int mt = 0; mt < 4; mt++) {
                const float* p = As + (mrow + mt * 16) * 36 + k0;
                a[mt][0] = p[0];
                a[mt][1] = p[8 * 36];
                a[mt][2] = p[4];
                a[mt][3] = p[8 * 36 + 4];
            }
            #pragma unroll
            for (int nt = 0; nt < 4; nt++) {
                const float* p = Bs + (nrow + nt * 8) * 36 + k0;
                b[nt][0] = p[0];
                b[nt][1] = p[4];
            }
            #pragma unroll
            for (int mt = 0; mt < 4; mt++)
                #pragma unroll
                for (int nt = 0; nt < 4; nt++)
                    mma1688(acc[mt][nt], a[mt], b[nt]);
        }
        __syncthreads();
    }

    // epilogue: registers -> global with fused bias / gelu / residual
    #pragma unroll
    for (int mt = 0; mt < 4; mt++) {
        int r0 = cM * 128 + wm * 64 + mt * 16 + gid;
        #pragma unroll
        for (int nt = 0; nt < 4; nt++) {
            int col = cN * 128 + wn * 32 + nt * 8 + 2 * tig;
            float2 bv = *(const float2*)(bias + col);
            float v0 = acc[mt][nt][0] + bv.x;
            float v1 = acc[mt][nt][1] + bv.y;
            float v2 = acc[mt][nt][2] + bv.x;
            float v3 = acc[mt][nt][3] + bv.y;
            size_t o0 = (size_t)r0 * N + col;
            size_t o1 = (size_t)(r0 + 8) * N + col;
            if (epi == EPI_GELU) {
                v0 = to_tf32(gelu1(v0)); v1 = to_tf32(gelu1(v1));
                v2 = to_tf32(gelu1(v2)); v3 = to_tf32(gelu1(v3));
            } else if (epi == EPI_RES) {
                float2 r0v = *(const float2*)(res + o0);
                float2 r1v = *(const float2*)(res + o1);
                v0 = r0v.x + scale * v0; v1 = r0v.y + scale * v1;
                v2 = r1v.x + scale * v2; v3 = r1v.y + scale * v3;
            }
            *(float2*)(C + o0) = make_float2(v0, v1);
            *(float2*)(C + o1) = make_float2(v2, v3);
        }
    }
}

// ---------------- block-local causal attention (64x64 blocks) ----------------
__global__ __launch_bounds__(256) void attn_kernel(
    const float* __restrict__ Q, const float* __restrict__ K,
    const float* __restrict__ V, float* __restrict__ O)
{
    __shared__ float Qs[64 * 64];
    __shared__ float Kt[64 * 64];
    __shared__ float Ss[64 * 64];

    int blk = blockIdx.x, h = blockIdx.y, b = blockIdx.z;
    int tid = threadIdx.x;
    size_t base = ((size_t)(b * SEQ + blk * 64) * NHEAD + h) * 64;

    for (int t = tid; t < 4096; t += 256) {
        int s = t >> 6, d = t & 63;
        Qs[s * 64 + d] = Q[base + (size_t)s * 1024 + d];
        Kt[d * 64 + ((s + d) & 63)] = K[base + (size_t)s * 1024 + d];
    }
    __syncthreads();

    int tr = tid >> 4, tc = tid & 15;
    float acc[4][4] = {};
    #pragma unroll 4
    for (int kk = 0; kk < 64; kk++) {
        float qa[4], kb[4];
        #pragma unroll
        for (int i = 0; i < 4; i++) qa[i] = Qs[(tr * 4 + i) * 64 + kk];
        #pragma unroll
        for (int j = 0; j < 4; j++) kb[j] = Kt[kk * 64 + ((tc * 4 + j + kk) & 63)];
        #pragma unroll
        for (int i = 0; i < 4; i++)
            #pragma unroll
            for (int j = 0; j < 4; j++)
                acc[i][j] = fmaf(qa[i], kb[j], acc[i][j]);
    }
    #pragma unroll
    for (int i = 0; i < 4; i++)
        #pragma unroll
        for (int j = 0; j < 4; j++)
            Ss[(tr * 4 + i) * 64 + tc * 4 + j] = acc[i][j] * 0.125f;
    __syncthreads();

    int warp = tid >> 5, lane = tid & 31;
    for (int i = warp; i < 64; i += 8) {
        float v0 = Ss[i * 64 + lane];
        float v1 = Ss[i * 64 + lane + 32];
        bool  m0 = (lane <= i), m1 = (lane + 32 <= i);
        float a0 = m0 ? v0 : -INFINITY;
        float a1 = m1 ? v1 : -INFINITY;
        float m = fmaxf(a0, a1);
        #pragma unroll
        for (int o = 16; o > 0; o >>= 1) m = fmaxf(m, __shfl_xor_sync(0xffffffffu, m, o));
        float e0 = m0 ? expf(v0 - m) : 0.f;
        float e1 = m1 ? expf(v1 - m) : 0.f;
        float sum = e0 + e1;
        #pragma unroll
        for (int o = 16; o > 0; o >>= 1) sum += __shfl_xor_sync(0xffffffffu, sum, o);
        float inv = 1.0f / sum;
        Ss[i * 64 + lane]      = e0 * inv;
        Ss[i * 64 + lane + 32] = e1 * inv;
    }
    __syncthreads();

    for (int t = tid; t < 4096; t += 256) {
        int s = t >> 6, d = t & 63;
        Qs[s * 64 + d] = V[base + (size_t)s * 1024 + d];
    }
    __syncthreads();

    float cacc[4][4] = {};
    for (int j = 0; j < 64; j++) {
        float p[4], vv[4];
        #pragma unroll
        for (int i = 0; i < 4; i++) p[i] = Ss[(tr * 4 + i) * 64 + j];
        #pragma unroll
        for (int d = 0; d < 4; d++) vv[d] = Qs[j * 64 + tc * 4 + d];
        #pragma unroll
        for (int i = 0; i < 4; i++)
            #pragma unroll
            for (int d = 0; d < 4; d++)
                cacc[i][d] = fmaf(p[i], vv[d], cacc[i][d]);
    }
    #pragma unroll
    for (int i = 0; i < 4; i++)
        #pragma unroll
        for (int d = 0; d < 4; d++)
            O[base + (size_t)(tr * 4 + i) * 1024 + tc * 4 + d] = to_tf32(cacc[i][d]);
}

// ---------------- launcher ----------------
extern "C" void kernel_launch(void* const* d_in, const int* in_sizes, int n_in,
                              void* d_out, int out_size)
{
    const float* x    = (const float*)d_in[0];
    const float* Wq   = (const float*)d_in[2];
    const float* bq   = (const float*)d_in[3];
    const float* Wk   = (const float*)d_in[4];
    const float* bk   = (const float*)d_in[5];
    const float* Wv   = (const float*)d_in[6];
    const float* bv   = (const float*)d_in[7];
    const float* Wo   = (const float*)d_in[8];
    const float* bo   = (const float*)d_in[9];
    const float* ln1g = (const float*)d_in[10];
    const float* ln1b = (const float*)d_in[11];
    const float* ln2g = (const float*)d_in[12];
    const float* ln2b = (const float*)d_in[13];
    const float* W1   = (const float*)d_in[14];
    const float* b1   = (const float*)d_in[15];
    const float* W2   = (const float*)d_in[16];
    const float* b2   = (const float*)d_in[17];
    float* out = (float*)d_out;

    float *ph, *pq, *pk, *pv, *pctx, *px1, *pf;
    float *wqt, *wkt, *wvt, *wot, *w1t, *w2t;
    cudaGetSymbolAddress((void**)&ph,   g_h);
    cudaGetSymbolAddress((void**)&pq,   g_q);
    cudaGetSymbolAddress((void**)&pk,   g_k);
    cudaGetSymbolAddress((void**)&pv,   g_v);
    cudaGetSymbolAddress((void**)&pctx, g_ctx);
    cudaGetSymbolAddress((void**)&px1,  g_x1);
    cudaGetSymbolAddress((void**)&pf,   g_f);
    cudaGetSymbolAddress((void**)&wqt,  g_wqt);
    cudaGetSymbolAddress((void**)&wkt,  g_wkt);
    cudaGetSymbolAddress((void**)&wvt,  g_wvt);
    cudaGetSymbolAddress((void**)&wot,  g_wot);
    cudaGetSymbolAddress((void**)&w1t,  g_w1t);
    cudaGetSymbolAddress((void**)&w2t,  g_w2t);

    cudaFuncSetAttribute(gemm_mma, cudaFuncAttributeMaxDynamicSharedMemorySize, SMEM_GEMM);

    dim3 tb(32, 8);
    transpose_rt<<<dim3(DMODEL/32, DMODEL/32), tb>>>(Wq, wqt, DMODEL, DMODEL);
    transpose_rt<<<dim3(DMODEL/32, DMODEL/32), tb>>>(Wk, wkt, DMODEL, DMODEL);
    transpose_rt<<<dim3(DMODEL/32, DMODEL/32), tb>>>(Wv, wvt, DMODEL, DMODEL);
    transpose_rt<<<dim3(DMODEL/32, DMODEL/32), tb>>>(Wo, wot, DMODEL, DMODEL);
    transpose_rt<<<dim3(DFF/32,    DMODEL/32), tb>>>(W1, w1t, DMODEL, DFF);    // -> [4096,1024]
    transpose_rt<<<dim3(DMODEL/32, DFF/32),    tb>>>(W2, w2t, DFF, DMODEL);    // -> [1024,4096]

    dim3 gD(DMODEL/128, MROWS/128);   // (8, 32)
    dim3 gF(DFF/128,    MROWS/128);   // (32, 32)

    // sublayer 1
    layernorm_kernel<<<MROWS, 256>>>(x, ln1g, ln1b, ph);
    gemm_mma<<<gD, 256, SMEM_GEMM>>>(DMODEL, DMODEL, ph, wqt, bq, nullptr, pq, 0.f, EPI_BIAS);
    gemm_mma<<<gD, 256, SMEM_GEMM>>>(DMODEL, DMODEL, ph, wkt, bk, nullptr, pk, 0.f, EPI_BIAS);
    gemm_mma<<<gD, 256, SMEM_GEMM>>>(DMODEL, DMODEL, ph, wvt, bv, nullptr, pv, 0.f, EPI_BIAS);
    attn_kernel<<<dim3(SEQ/64, NHEAD, BSZ), 256>>>(pq, pk, pv, pctx);
    gemm_mma<<<gD, 256, SMEM_GEMM>>>(DMODEL, DMODEL, pctx, wot, bo, x, px1, RES_SCALE, EPI_RES);

    // sublayer 2
    layernorm_kernel<<<MROWS, 256>>>(px1, ln2g, ln2b, ph);
    gemm_mma<<<gF, 256, SMEM_GEMM>>>(DMODEL, DFF, ph, w1t, b1, nullptr, pf, 0.f, EPI_GELU);
    gemm_mma<<<gD, 256, SMEM_GEMM>>>(DFF, DMODEL, pf, w2t, b2, px1, out, RES_SCALE, EPI_RES);
}